// round 13
// baseline (speedup 1.0000x reference)
#include <cuda_runtime.h>
#include <cuda_bf16.h>
#include <math.h>
#include <stdint.h>

#define BATCH   32
#define DIM     2048
#define NH      32
#define NKV     8
#define HD      64
#define REP     4
#define MAXS    2048
#define SP      2047
#define NSPLIT  8
#define CHUNK   256
#define TILE    64
#define NT      (CHUNK / TILE)
#define KSPLIT  8
#define KCHUNK  (DIM / KSPLIT)    // 256

// ---------------- scratch ----------------
__device__ __align__(16) float g_qkv_part[KSPLIT * BATCH * 3072];
__device__ __align__(16) float g_part_o [BATCH * NKV * NSPLIT * REP * HD];
__device__ __align__(16) float g_part_s [BATCH * NKV * NSPLIT * REP];
__device__ __align__(16) float g_o_part [KSPLIT * BATCH * DIM];
__device__ int g_ocnt[16];     // zero-initialized at load; self-reset each run

__device__ __forceinline__ void cpasync16(uint32_t dst, const void* src) {
    asm volatile("cp.async.cg.shared.global [%0], [%1], 16;\n" :: "r"(dst), "l"(src));
}
__device__ __forceinline__ void cpasync_commit() { asm volatile("cp.async.commit_group;\n"); }
template<int N>
__device__ __forceinline__ void cpasync_wait() { asm volatile("cp.async.wait_group %0;\n" :: "n"(N)); }

// ---------------- tensor-core helpers ----------------
__device__ __forceinline__ void ldmx4(unsigned* r, unsigned addr) {
    asm volatile("ldmatrix.sync.aligned.m8n8.x4.shared.b16 {%0,%1,%2,%3}, [%4];"
        : "=r"(r[0]), "=r"(r[1]), "=r"(r[2]), "=r"(r[3]) : "r"(addr));
}
__device__ __forceinline__ void ldmx2t(unsigned* r, unsigned addr) {
    asm volatile("ldmatrix.sync.aligned.m8n8.x2.trans.shared.b16 {%0,%1}, [%2];"
        : "=r"(r[0]), "=r"(r[1]) : "r"(addr));
}
__device__ __forceinline__ void mma_bf16(float* c, const unsigned* a, const unsigned* b) {
    asm volatile(
        "mma.sync.aligned.m16n8k16.row.col.f32.bf16.bf16.f32 "
        "{%0,%1,%2,%3}, {%4,%5,%6,%7}, {%8,%9}, {%0,%1,%2,%3};"
        : "+f"(c[0]), "+f"(c[1]), "+f"(c[2]), "+f"(c[3])
        : "r"(a[0]), "r"(a[1]), "r"(a[2]), "r"(a[3]), "r"(b[0]), "r"(b[1]));
}

#define XSTR 72
#define WSTR 136

struct GemmSmem {
    __nv_bfloat16 XsH[32][XSTR], XsL[32][XSTR];
    __nv_bfloat16 WsH[64][WSTR], WsL[64][WSTR];
};

__device__ __forceinline__ void gemm_mma_steps(GemmSmem* sm, int lane, int wid, float acc[2][2][4]) {
    const unsigned xsH = (unsigned)__cvta_generic_to_shared(&sm->XsH[0][0]);
    const unsigned xsL = (unsigned)__cvta_generic_to_shared(&sm->XsL[0][0]);
    const unsigned wsH = (unsigned)__cvta_generic_to_shared(&sm->WsH[0][0]);
    const unsigned wsL = (unsigned)__cvta_generic_to_shared(&sm->WsL[0][0]);
    #pragma unroll
    for (int s = 0; s < 4; ++s) {
        unsigned aH0[4], aH1[4], aL0[4], aL1[4];
        {
            int msel = lane >> 3, rsel = lane & 7;
            int row = rsel + ((msel & 1) << 3);
            int colhw = s * 16 + ((msel >> 1) << 3);
            unsigned o0 = (unsigned)(( row       * XSTR + colhw) * 2);
            unsigned o1 = (unsigned)(((row + 16) * XSTR + colhw) * 2);
            ldmx4(aH0, xsH + o0); ldmx4(aH1, xsH + o1);
            ldmx4(aL0, xsL + o0); ldmx4(aL1, xsL + o1);
        }
        unsigned bH0[2], bH1[2], bL0[2], bL1[2];
        {
            int rsel = lane & 7, ksel = (lane >> 3) & 1;
            int krow = s * 16 + (ksel << 3) + rsel;
            unsigned oA = (unsigned)((krow * WSTR + wid * 16    ) * 2);
            unsigned oB = (unsigned)((krow * WSTR + wid * 16 + 8) * 2);
            ldmx2t(bH0, wsH + oA); ldmx2t(bH1, wsH + oB);
            ldmx2t(bL0, wsL + oA); ldmx2t(bL1, wsL + oB);
        }
        mma_bf16(acc[0][0], aH0, bH0); mma_bf16(acc[0][1], aH0, bH1);
        mma_bf16(acc[1][0], aH1, bH0); mma_bf16(acc[1][1], aH1, bH1);
        mma_bf16(acc[0][0], aH0, bL0); mma_bf16(acc[0][1], aH0, bL1);
        mma_bf16(acc[1][0], aH1, bL0); mma_bf16(acc[1][1], aH1, bL1);
        mma_bf16(acc[0][0], aL0, bH0); mma_bf16(acc[0][1], aL0, bH1);
        mma_bf16(acc[1][0], aL1, bH0); mma_bf16(acc[1][1], aL1, bH1);
    }
}

__device__ __forceinline__ void split_store4(__nv_bfloat16* dH, __nv_bfloat16* dL, float4 v) {
    float vv[4] = {v.x, v.y, v.z, v.w};
    #pragma unroll
    for (int j = 0; j < 4; ++j) {
        __nv_bfloat16 h = __float2bfloat16(vv[j]);
        dH[j] = h;
        dL[j] = __float2bfloat16(vv[j] - __bfloat162float(h));
    }
}

// ---------------- QKV GEMM ----------------
__global__ __launch_bounds__(256) void gemm_qkv_kernel(
    const float* __restrict__ X, const float* __restrict__ W0,
    const float* __restrict__ W1, const float* __restrict__ W2)
{
    __shared__ GemmSmem sm;

    const int jbase = blockIdx.x * 128;
    const float* W = W0; int wcols = DIM; int jloc = jbase;
    if (jbase >= 2560)      { W = W2; wcols = 512; jloc = jbase - 2560; }
    else if (jbase >= 2048) { W = W1; wcols = 512; jloc = jbase - 2048; }

    const int t = threadIdx.x, lane = t & 31, wid = t >> 5;
    const int kbeg = blockIdx.y * KCHUNK;

    float acc[2][2][4];
    #pragma unroll
    for (int m = 0; m < 2; ++m)
        #pragma unroll
        for (int n = 0; n < 2; ++n)
            #pragma unroll
            for (int i = 0; i < 4; ++i) acc[m][n][i] = 0.f;

    for (int kb = 0; kb < KCHUNK / 64; ++kb) {
        const int k0 = kbeg + kb * 64;
        #pragma unroll
        for (int i = 0; i < 2; ++i) {
            int idx = i * 256 + t;
            int m = idx >> 4, c = (idx & 15) << 2;
            float4 v = *(const float4*)&X[m * DIM + k0 + c];
            split_store4(&sm.XsH[m][c], &sm.XsL[m][c], v);
        }
        #pragma unroll
        for (int i = 0; i < 8; ++i) {
            int idx = i * 256 + t;
            int kk = idx >> 5, nc = (idx & 31) << 2;
            float4 v = *(const float4*)&W[(size_t)(k0 + kk) * wcols + jloc + nc];
            split_store4(&sm.WsH[kk][nc], &sm.WsL[kk][nc], v);
        }
        __syncthreads();
        gemm_mma_steps(&sm, lane, wid, acc);
        __syncthreads();
    }

    const int gid = lane >> 2, tig = lane & 3;
    const int ks = blockIdx.y;
    #pragma unroll
    for (int m = 0; m < 2; ++m) {
        int row = m * 16 + gid;
        #pragma unroll
        for (int n = 0; n < 2; ++n) {
            int col = jbase + wid * 16 + n * 8 + tig * 2;
            *(float2*)&g_qkv_part[(size_t)(ks * 32 + row    ) * 3072 + col]
                = make_float2(acc[m][n][0], acc[m][n][1]);
            *(float2*)&g_qkv_part[(size_t)(ks * 32 + row + 8) * 3072 + col]
                = make_float2(acc[m][n][2], acc[m][n][3]);
        }
    }
}

// ---------------- flash-decode attention: barrier-free warp-owned tiles ----------------
__global__ __launch_bounds__(256) void attn_kernel(
    const float* __restrict__ cache_k, const float* __restrict__ cache_v)
{
    __shared__ __align__(16) float Vsh[2][TILE][HD + 4];   // obuf aliases Vsh[0] at end
    __shared__ __align__(16) float pshw[8][32];            // [warp][row_local*4 + head]
    __shared__ float wreds[8][4];
    __shared__ __align__(16) float qsm[256];
    __shared__ __align__(16) float knsm[64], vnsm[64];

    const int split = blockIdx.x, kv = blockIdx.y, b = blockIdx.z;
    const int t = threadIdx.x;
    const int lane = t & 31, warp = t >> 5;
    const int c4 = lane & 15;
    const int r2 = lane >> 4;
    const int wbase = warp * 8;

    // ---- fused RoPE prologue ----
    if (t < 192) {
        int j, isK = 0, isV = 0, pi = 0;
        if (t < 128)      { j = kv * 256 + 2 * t; pi = 2 * t; }
        else if (t < 160) { pi = 2 * (t - 128); j = 2048 + kv * 64 + pi; isK = 1; }
        else              { pi = 2 * (t - 160); j = 2560 + kv * 64 + pi; isV = 1; }
        float v0 = 0.f, v1 = 0.f;
        #pragma unroll
        for (int s = 0; s < KSPLIT; ++s) {
            float2 p = *(const float2*)&g_qkv_part[(s * BATCH + b) * 3072 + j];
            v0 += p.x; v1 += p.y;
        }
        if (isV) {
            vnsm[pi] = v0; vnsm[pi + 1] = v1;
        } else {
            int i2 = j & 63;
            float inv = exp2f(-(float)i2 * (13.287712379549449f / 64.f));
            float sn, cs;
            sincosf(2047.0f * inv, &sn, &cs);
            float r0 = v0 * cs - v1 * sn;
            float r1 = v0 * sn + v1 * cs;
            if (isK) { knsm[pi] = r0; knsm[pi + 1] = r1; }
            else     { qsm[pi] = r0 * 0.125f; qsm[pi + 1] = r1 * 0.125f; }
        }
    }
    __syncthreads();

    const float* kbase = cache_k + (size_t)b * MAXS * NKV * HD + kv * HD;
    const float* vbase = cache_v + (size_t)b * MAXS * NKV * HD + kv * HD;
    const int lbase = split * CHUNK;

    float4 qf[4];
    #pragma unroll
    for (int h = 0; h < 4; ++h)
        qf[h] = *(const float4*)&qsm[(h << 6) + (c4 << 2)];

    float oa[4][2];
    #pragma unroll
    for (int h = 0; h < 4; ++h) { oa[h][0] = 0.f; oa[h][1] = 0.f; }
    float s_acc = 0.f;

    // ---- prologue: V(0) + K(0) for this warp's rows ----
    #pragma unroll
    for (int i = 0; i < 4; ++i) {
        int row = wbase + r2 + (i << 1);
        cpasync16((uint32_t)__cvta_generic_to_shared(&Vsh[0][row][c4 << 2]),
                  (const void*)(vbase + (size_t)(lbase + row) * 512 + (c4 << 2)));
    }
    cpasync_commit();
    float4 kk[4];
    #pragma unroll
    for (int i = 0; i < 4; ++i) {
        int row = wbase + r2 + (i << 1);
        int l = lbase + row;
        const float4* p = (l == SP) ? (const float4*)&knsm[c4 << 2]
                                    : (const float4*)(kbase + (size_t)l * 512 + (c4 << 2));
        kk[i] = *p;
    }

    #pragma unroll
    for (int tt = 0; tt < NT; ++tt) {
        const int buf = tt & 1;
        const int l0 = lbase + tt * TILE;

        // V(tt+1): issue FIRST for maximum latency cover. buf^1 is free —
        // its last readers were this warp's own o-phase(tt-1), program-ordered.
        if (tt < NT - 1) {
            #pragma unroll
            for (int i = 0; i < 4; ++i) {
                int row = wbase + r2 + (i << 1);
                cpasync16((uint32_t)__cvta_generic_to_shared(&Vsh[buf ^ 1][row][c4 << 2]),
                          (const void*)(vbase + (size_t)(l0 + TILE + row) * 512 + (c4 << 2)));
            }
            cpasync_commit();
        }

        // K prefetch for tile tt+1 (regs)
        float4 kk2[4];
        if (tt < NT - 1) {
            #pragma unroll
            for (int i = 0; i < 4; ++i) {
                int row = wbase + r2 + (i << 1);
                int l = l0 + TILE + row;
                const float4* p = (l == SP) ? (const float4*)&knsm[c4 << 2]
                                            : (const float4*)(kbase + (size_t)l * 512 + (c4 << 2));
                kk2[i] = *p;
            }
        }

        // ---- scores: partial dots + 15-shfl reduce-scatter over c4 ----
        float pf[16];
        #pragma unroll
        for (int h = 0; h < 4; ++h)
            #pragma unroll
            for (int i = 0; i < 4; ++i) {
                float s = kk[i].x * qf[h].x;
                s += kk[i].y * qf[h].y;
                s += kk[i].z * qf[h].z;
                s += kk[i].w * qf[h].w;
                pf[(h << 2) | i] = s;
            }
        float r8[8];
        #pragma unroll
        for (int j = 0; j < 8; ++j) {
            float snd = (c4 & 1) ? pf[2*j] : pf[2*j+1];
            float kp  = (c4 & 1) ? pf[2*j+1] : pf[2*j];
            r8[j] = kp + __shfl_xor_sync(0xffffffffu, snd, 1);
        }
        float r4[4];
        #pragma unroll
        for (int j = 0; j < 4; ++j) {
            float snd = (c4 & 2) ? r8[2*j] : r8[2*j+1];
            float kp  = (c4 & 2) ? r8[2*j+1] : r8[2*j];
            r4[j] = kp + __shfl_xor_sync(0xffffffffu, snd, 2);
        }
        float r2v[2];
        #pragma unroll
        for (int j = 0; j < 2; ++j) {
            float snd = (c4 & 4) ? r4[2*j] : r4[2*j+1];
            float kp  = (c4 & 4) ? r4[2*j+1] : r4[2*j];
            r2v[j] = kp + __shfl_xor_sync(0xffffffffu, snd, 4);
        }
        float sc;
        {
            float snd = (c4 & 8) ? r2v[0] : r2v[1];
            float kp  = (c4 & 8) ? r2v[1] : r2v[0];
            sc = kp + __shfl_xor_sync(0xffffffffu, snd, 8);
        }

        float ph = __expf(sc);
        pshw[warp][(r2 + ((c4 & 3) << 1)) * 4 + (c4 >> 2)] = ph;
        s_acc += ph;

        if (tt < NT - 1) cpasync_wait<1>();   // waits V(tt); V(tt+1) stays in flight
        else             cpasync_wait<0>();
        // patch the new-token V row (row 63 = warp 7, last tile of last split)
        if (l0 + 63 == SP && warp == 7)
            *(float2*)&Vsh[buf][63][lane << 1] = *(const float2*)&vnsm[lane << 1];
        __syncwarp();

        // ---- o-phase: this warp's 8 rows, 4 heads, 2 d's per lane ----
        #pragma unroll
        for (int r = 0; r < 8; ++r) {
            float4 p4 = *(const float4*)&pshw[warp][r << 2];
            float2 v2 = *(const float2*)&Vsh[buf][wbase + r][lane << 1];
            oa[0][0] += p4.x * v2.x; oa[0][1] += p4.x * v2.y;
            oa[1][0] += p4.y * v2.x; oa[1][1] += p4.y * v2.y;
            oa[2][0] += p4.z * v2.x; oa[2][1] += p4.z * v2.y;
            oa[3][0] += p4.w * v2.x; oa[3][1] += p4.w * v2.y;
        }
        __syncwarp();

        kk[0] = kk2[0]; kk[1] = kk2[1]; kk[2] = kk2[2]; kk[3] = kk2[3];
    }

    {
        float ps = s_acc;
        ps += __shfl_xor_sync(0xffffffffu, ps, 1);
        ps += __shfl_xor_sync(0xffffffffu, ps, 2);
        ps += __shfl_xor_sync(0xffffffffu, ps, 16);
        if ((lane & 3) == 0 && (lane & 16) == 0) wreds[warp][lane >> 2] = ps;
    }

    __syncthreads();
    float (*obuf)[256] = (float(*)[256])&Vsh[0][0][0];
    #pragma unroll
    for (int h = 0; h < 4; ++h)
        *(float2*)&obuf[warp][(h << 6) + (lane << 1)] = make_float2(oa[h][0], oa[h][1]);
    __syncthreads();
    {
        int h = t >> 6, dd = t & 63;
        float oo = 0.f;
        #pragma unroll
        for (int w = 0; w < 8; ++w) oo += obuf[w][t];
        g_part_o[(((b * NKV + kv) * NSPLIT + split) * REP + h) * HD + dd] = oo;
    }
    if (t < REP) {
        float ssum = 0.f;
        #pragma unroll
        for (int w = 0; w < 8; ++w) ssum += wreds[w][t];
        g_part_s[((b * NKV + kv) * NSPLIT + split) * REP + t] = ssum;
    }
}

// ---------------- O GEMM: fused split-combine input AND fused final reduce ----------------
__global__ __launch_bounds__(256) void gemm_o_kernel(const float* __restrict__ W,
                                                     float* __restrict__ out)
{
    __shared__ GemmSmem sm;
    __shared__ float srcp[32][4];
    __shared__ int isLast;

    const int jbase = blockIdx.x * 128;
    const int t = threadIdx.x, lane = t & 31, wid = t >> 5;
    const int kvg = blockIdx.y;
    const int kbeg = kvg * KCHUNK;

    if (t < 128) {
        int m = t >> 2, hh = t & 3;
        float S = 0.f;
        #pragma unroll
        for (int s = 0; s < NSPLIT; ++s)
            S += g_part_s[((m * NKV + kvg) * NSPLIT + s) * REP + hh];
        srcp[m][hh] = 1.f / S;
    }
    __syncthreads();

    float acc[2][2][4];
    #pragma unroll
    for (int m = 0; m < 2; ++m)
        #pragma unroll
        for (int n = 0; n < 2; ++n)
            #pragma unroll
            for (int i = 0; i < 4; ++i) acc[m][n][i] = 0.f;

    for (int kb = 0; kb < 4; ++kb) {
        const int k0 = kbeg + kb * 64;
        const int h = kb;
        #pragma unroll
        for (int i = 0; i < 2; ++i) {
            int idx = i * 256 + t;
            int m = idx >> 4, c = (idx & 15) << 2;
            float4 a = make_float4(0.f, 0.f, 0.f, 0.f);
            #pragma unroll
            for (int s = 0; s < NSPLIT; ++s) {
                float4 p = *(const float4*)
                    &g_part_o[(((m * NKV + kvg) * NSPLIT + s) * REP + h) * HD + c];
                a.x += p.x; a.y += p.y; a.z += p.z; a.w += p.w;
            }
            float r = srcp[m][h];
            a.x *= r; a.y *= r; a.z *= r; a.w *= r;
            split_store4(&sm.XsH[m][c], &sm.XsL[m][c], a);
        }
        #pragma unroll
        for (int i = 0; i < 8; ++i) {
            int idx = i * 256 + t;
            int kk = idx >> 5, nc = (idx & 31) << 2;
            float4 v = *(const float4*)&W[(size_t)(k0 + kk) * DIM + jbase + nc];
            split_store4(&sm.WsH[kk][nc], &sm.WsL[kk][nc], v);
        }
        __syncthreads();
        gemm_mma_steps(&sm, lane, wid, acc);
        __syncthreads();
    }

    // write k-split partial
    const int gid = lane >> 2, tig = lane & 3;
    const int ks = blockIdx.y;
    #pragma unroll
    for (int m = 0; m < 2; ++m) {
        int row = m * 16 + gid;
        #pragma unroll
        for (int n = 0; n < 2; ++n) {
            int col = jbase + wid * 16 + n * 8 + tig * 2;
            *(float2*)&g_o_part[(size_t)(ks * 32 + row    ) * DIM + col]
                = make_float2(acc[m][n][0], acc[m][n][1]);
            *(float2*)&g_o_part[(size_t)(ks * 32 + row + 8) * DIM + col]
                = make_float2(acc[m][n][2], acc[m][n][3]);
        }
    }

    // threadfence-reduction: last block for this j-tile sums the 8 partials
    __threadfence();
    if (t == 0) {
        int old = atomicAdd(&g_ocnt[blockIdx.x], 1);
        isLast = (old == KSPLIT - 1);
    }
    __syncthreads();
    if (isLast) {
        // j-tile = 32 rows x 128 cols = 1024 float4s; 4 per thread
        for (int i = t; i < 1024; i += 256) {
            int row = i >> 5, c4o = (i & 31) << 2;
            float4 v = make_float4(0.f, 0.f, 0.f, 0.f);
            #pragma unroll
            for (int s = 0; s < KSPLIT; ++s) {
                float4 p = *(const float4*)&g_o_part[(size_t)(s * 32 + row) * DIM + jbase + c4o];
                v.x += p.x; v.y += p.y; v.z += p.z; v.w += p.w;
            }
            *(float4*)&out[(size_t)row * DIM + jbase + c4o] = v;
        }
        if (t == 0) g_ocnt[blockIdx.x] = 0;   // self-reset for next graph replay
    }
}

// ---------------- launch ----------------
extern "C" void kernel_launch(void* const* d_in, const int* in_sizes, int n_in,
                              void* d_out, int out_size)
{
    const float* x  = (const float*)d_in[0];
    const float* qw = (const float*)d_in[1];
    const float* kw = (const float*)d_in[2];
    const float* vw = (const float*)d_in[3];
    const float* ow = (const float*)d_in[4];
    const float* ck = (const float*)d_in[5];
    const float* cv = (const float*)d_in[6];
    float* out = (float*)d_out;

    gemm_qkv_kernel<<<dim3(24, KSPLIT), 256>>>(x, qw, kw, vw);
    attn_kernel<<<dim3(NSPLIT, NKV, BATCH), 256>>>(ck, cv);
    gemm_o_kernel<<<dim3(16, KSPLIT), 256>>>(ow, out);
}

// round 14
// speedup vs baseline: 1.1831x; 1.1831x over previous
#include <cuda_runtime.h>
#include <cuda_bf16.h>
#include <math.h>
#include <stdint.h>

#define BATCH   32
#define DIM     2048
#define NH      32
#define NKV     8
#define HD      64
#define REP     4
#define MAXS    2048
#define SP      2047
#define NSPLIT  8
#define CHUNK   256
#define TILE    64
#define NT      (CHUNK / TILE)
#define KSPLIT  8                  // O-proj split-K
#define KCHUNK  (DIM / KSPLIT)     // 256
#define QKSPL   16                 // QKV split-K (grid 24x16 = 384 blocks)
#define QKCH    (DIM / QKSPL)      // 128 -> 2 k-tiles of 64

// ---------------- scratch ----------------
__device__ __align__(16) float g_qkv_part[QKSPL * BATCH * 3072];
__device__ __align__(16) float g_part_o [BATCH * NKV * NSPLIT * REP * HD];
__device__ __align__(16) float g_part_s [BATCH * NKV * NSPLIT * REP];
__device__ __align__(16) float g_o_part [KSPLIT * BATCH * DIM];

__device__ __forceinline__ void cpasync16(uint32_t dst, const void* src) {
    asm volatile("cp.async.cg.shared.global [%0], [%1], 16;\n" :: "r"(dst), "l"(src));
}
__device__ __forceinline__ void cpasync_commit() { asm volatile("cp.async.commit_group;\n"); }
template<int N>
__device__ __forceinline__ void cpasync_wait() { asm volatile("cp.async.wait_group %0;\n" :: "n"(N)); }

// ---------------- tensor-core helpers ----------------
__device__ __forceinline__ void ldmx4(unsigned* r, unsigned addr) {
    asm volatile("ldmatrix.sync.aligned.m8n8.x4.shared.b16 {%0,%1,%2,%3}, [%4];"
        : "=r"(r[0]), "=r"(r[1]), "=r"(r[2]), "=r"(r[3]) : "r"(addr));
}
__device__ __forceinline__ void ldmx2t(unsigned* r, unsigned addr) {
    asm volatile("ldmatrix.sync.aligned.m8n8.x2.trans.shared.b16 {%0,%1}, [%2];"
        : "=r"(r[0]), "=r"(r[1]) : "r"(addr));
}
__device__ __forceinline__ void mma_bf16(float* c, const unsigned* a, const unsigned* b) {
    asm volatile(
        "mma.sync.aligned.m16n8k16.row.col.f32.bf16.bf16.f32 "
        "{%0,%1,%2,%3}, {%4,%5,%6,%7}, {%8,%9}, {%0,%1,%2,%3};"
        : "+f"(c[0]), "+f"(c[1]), "+f"(c[2]), "+f"(c[3])
        : "r"(a[0]), "r"(a[1]), "r"(a[2]), "r"(a[3]), "r"(b[0]), "r"(b[1]));
}

#define XSTR 72
#define WSTR 136

struct GemmSmem {
    __nv_bfloat16 XsH[32][XSTR], XsL[32][XSTR];
    __nv_bfloat16 WsH[64][WSTR], WsL[64][WSTR];
};

__device__ __forceinline__ void gemm_mma_steps(GemmSmem* sm, int lane, int wid, float acc[2][2][4]) {
    const unsigned xsH = (unsigned)__cvta_generic_to_shared(&sm->XsH[0][0]);
    const unsigned xsL = (unsigned)__cvta_generic_to_shared(&sm->XsL[0][0]);
    const unsigned wsH = (unsigned)__cvta_generic_to_shared(&sm->WsH[0][0]);
    const unsigned wsL = (unsigned)__cvta_generic_to_shared(&sm->WsL[0][0]);
    #pragma unroll
    for (int s = 0; s < 4; ++s) {
        unsigned aH0[4], aH1[4], aL0[4], aL1[4];
        {
            int msel = lane >> 3, rsel = lane & 7;
            int row = rsel + ((msel & 1) << 3);
            int colhw = s * 16 + ((msel >> 1) << 3);
            unsigned o0 = (unsigned)(( row       * XSTR + colhw) * 2);
            unsigned o1 = (unsigned)(((row + 16) * XSTR + colhw) * 2);
            ldmx4(aH0, xsH + o0); ldmx4(aH1, xsH + o1);
            ldmx4(aL0, xsL + o0); ldmx4(aL1, xsL + o1);
        }
        unsigned bH0[2], bH1[2], bL0[2], bL1[2];
        {
            int rsel = lane & 7, ksel = (lane >> 3) & 1;
            int krow = s * 16 + (ksel << 3) + rsel;
            unsigned oA = (unsigned)((krow * WSTR + wid * 16    ) * 2);
            unsigned oB = (unsigned)((krow * WSTR + wid * 16 + 8) * 2);
            ldmx2t(bH0, wsH + oA); ldmx2t(bH1, wsH + oB);
            ldmx2t(bL0, wsL + oA); ldmx2t(bL1, wsL + oB);
        }
        mma_bf16(acc[0][0], aH0, bH0); mma_bf16(acc[0][1], aH0, bH1);
        mma_bf16(acc[1][0], aH1, bH0); mma_bf16(acc[1][1], aH1, bH1);
        mma_bf16(acc[0][0], aH0, bL0); mma_bf16(acc[0][1], aH0, bL1);
        mma_bf16(acc[1][0], aH1, bL0); mma_bf16(acc[1][1], aH1, bL1);
        mma_bf16(acc[0][0], aL0, bH0); mma_bf16(acc[0][1], aL0, bH1);
        mma_bf16(acc[1][0], aL1, bH0); mma_bf16(acc[1][1], aL1, bH1);
    }
}

__device__ __forceinline__ void split_store4(__nv_bfloat16* dH, __nv_bfloat16* dL, float4 v) {
    float vv[4] = {v.x, v.y, v.z, v.w};
    #pragma unroll
    for (int j = 0; j < 4; ++j) {
        __nv_bfloat16 h = __float2bfloat16(vv[j]);
        dH[j] = h;
        dL[j] = __float2bfloat16(vv[j] - __bfloat162float(h));
    }
}

// ---------------- QKV GEMM: split-K 16 + register-pipelined tile loads ----------------
// grid (24, QKSPL), block 256. Two 64-K tiles per block; tile kb+1's gmem loads
// are issued right after the first barrier and consumed after the MMA.
__global__ __launch_bounds__(256) void gemm_qkv_kernel(
    const float* __restrict__ X, const float* __restrict__ W0,
    const float* __restrict__ W1, const float* __restrict__ W2)
{
    __shared__ GemmSmem sm;

    const int jbase = blockIdx.x * 128;
    const float* W = W0; int wcols = DIM; int jloc = jbase;
    if (jbase >= 2560)      { W = W2; wcols = 512; jloc = jbase - 2560; }
    else if (jbase >= 2048) { W = W1; wcols = 512; jloc = jbase - 2048; }

    const int t = threadIdx.x, lane = t & 31, wid = t >> 5;
    const int kbeg = blockIdx.y * QKCH;

    // per-thread load geometry
    const int xm = t >> 4,          xc = (t & 15) << 2;    // X: 2 loads (i<<5 rows... )
    const int wk = t >> 5,          wc = (t & 31) << 2;    // W: 8 loads (+8 rows each)

    float acc[2][2][4];
    #pragma unroll
    for (int m = 0; m < 2; ++m)
        #pragma unroll
        for (int n = 0; n < 2; ++n)
            #pragma unroll
            for (int i = 0; i < 4; ++i) acc[m][n][i] = 0.f;

    // prologue loads for kb = 0
    float4 xr[2], wr[8];
    #pragma unroll
    for (int i = 0; i < 2; ++i)
        xr[i] = *(const float4*)&X[(xm + (i << 4)) * DIM + kbeg + xc];
    #pragma unroll
    for (int i = 0; i < 8; ++i)
        wr[i] = *(const float4*)&W[(size_t)(kbeg + wk + (i << 3)) * wcols + jloc + wc];

    #pragma unroll
    for (int kb = 0; kb < QKCH / 64; ++kb) {
        // store current tile regs -> smem (hi/lo split)
        #pragma unroll
        for (int i = 0; i < 2; ++i)
            split_store4(&sm.XsH[xm + (i << 4)][xc], &sm.XsL[xm + (i << 4)][xc], xr[i]);
        #pragma unroll
        for (int i = 0; i < 8; ++i)
            split_store4(&sm.WsH[wk + (i << 3)][wc], &sm.WsL[wk + (i << 3)][wc], wr[i]);
        __syncthreads();

        // issue next tile's gmem loads (overlap with MMA below)
        if (kb + 1 < QKCH / 64) {
            const int k0 = kbeg + (kb + 1) * 64;
            #pragma unroll
            for (int i = 0; i < 2; ++i)
                xr[i] = *(const float4*)&X[(xm + (i << 4)) * DIM + k0 + xc];
            #pragma unroll
            for (int i = 0; i < 8; ++i)
                wr[i] = *(const float4*)&W[(size_t)(k0 + wk + (i << 3)) * wcols + jloc + wc];
        }

        gemm_mma_steps(&sm, lane, wid, acc);
        __syncthreads();
    }

    const int gid = lane >> 2, tig = lane & 3;
    const int ks = blockIdx.y;
    #pragma unroll
    for (int m = 0; m < 2; ++m) {
        int row = m * 16 + gid;
        #pragma unroll
        for (int n = 0; n < 2; ++n) {
            int col = jbase + wid * 16 + n * 8 + tig * 2;
            *(float2*)&g_qkv_part[(size_t)(ks * 32 + row    ) * 3072 + col]
                = make_float2(acc[m][n][0], acc[m][n][1]);
            *(float2*)&g_qkv_part[(size_t)(ks * 32 + row + 8) * 3072 + col]
                = make_float2(acc[m][n][2], acc[m][n][3]);
        }
    }
}

// ---------------- flash-decode attention: barrier-free warp-owned tiles (86.5us version) ----
__global__ __launch_bounds__(256) void attn_kernel(
    const float* __restrict__ cache_k, const float* __restrict__ cache_v)
{
    __shared__ __align__(16) float Vsh[2][TILE][HD + 4];
    __shared__ __align__(16) float pshw[8][32];
    __shared__ float wreds[8][4];
    __shared__ __align__(16) float qsm[256];
    __shared__ __align__(16) float knsm[64], vnsm[64];

    const int split = blockIdx.x, kv = blockIdx.y, b = blockIdx.z;
    const int t = threadIdx.x;
    const int lane = t & 31, warp = t >> 5;
    const int c4 = lane & 15;
    const int r2 = lane >> 4;
    const int wbase = warp * 8;

    // ---- fused RoPE prologue (now sums QKSPL=16 partials) ----
    if (t < 192) {
        int j, isK = 0, isV = 0, pi = 0;
        if (t < 128)      { j = kv * 256 + 2 * t; pi = 2 * t; }
        else if (t < 160) { pi = 2 * (t - 128); j = 2048 + kv * 64 + pi; isK = 1; }
        else              { pi = 2 * (t - 160); j = 2560 + kv * 64 + pi; isV = 1; }
        float v0 = 0.f, v1 = 0.f;
        #pragma unroll
        for (int s = 0; s < QKSPL; ++s) {
            float2 p = *(const float2*)&g_qkv_part[(size_t)(s * BATCH + b) * 3072 + j];
            v0 += p.x; v1 += p.y;
        }
        if (isV) {
            vnsm[pi] = v0; vnsm[pi + 1] = v1;
        } else {
            int i2 = j & 63;
            float inv = exp2f(-(float)i2 * (13.287712379549449f / 64.f));
            float sn, cs;
            sincosf(2047.0f * inv, &sn, &cs);
            float r0 = v0 * cs - v1 * sn;
            float r1 = v0 * sn + v1 * cs;
            if (isK) { knsm[pi] = r0; knsm[pi + 1] = r1; }
            else     { qsm[pi] = r0 * 0.125f; qsm[pi + 1] = r1 * 0.125f; }
        }
    }
    __syncthreads();

    const float* kbase = cache_k + (size_t)b * MAXS * NKV * HD + kv * HD;
    const float* vbase = cache_v + (size_t)b * MAXS * NKV * HD + kv * HD;
    const int lbase = split * CHUNK;

    float4 qf[4];
    #pragma unroll
    for (int h = 0; h < 4; ++h)
        qf[h] = *(const float4*)&qsm[(h << 6) + (c4 << 2)];

    float oa[4][2];
    #pragma unroll
    for (int h = 0; h < 4; ++h) { oa[h][0] = 0.f; oa[h][1] = 0.f; }
    float s_acc = 0.f;

    #pragma unroll
    for (int i = 0; i < 4; ++i) {
        int row = wbase + r2 + (i << 1);
        cpasync16((uint32_t)__cvta_generic_to_shared(&Vsh[0][row][c4 << 2]),
                  (const void*)(vbase + (size_t)(lbase + row) * 512 + (c4 << 2)));
    }
    cpasync_commit();
    float4 kk[4];
    #pragma unroll
    for (int i = 0; i < 4; ++i) {
        int row = wbase + r2 + (i << 1);
        int l = lbase + row;
        const float4* p = (l == SP) ? (const float4*)&knsm[c4 << 2]
                                    : (const float4*)(kbase + (size_t)l * 512 + (c4 << 2));
        kk[i] = *p;
    }

    #pragma unroll
    for (int tt = 0; tt < NT; ++tt) {
        const int buf = tt & 1;
        const int l0 = lbase + tt * TILE;

        float4 kk2[4];
        if (tt < NT - 1) {
            #pragma unroll
            for (int i = 0; i < 4; ++i) {
                int row = wbase + r2 + (i << 1);
                int l = l0 + TILE + row;
                const float4* p = (l == SP) ? (const float4*)&knsm[c4 << 2]
                                            : (const float4*)(kbase + (size_t)l * 512 + (c4 << 2));
                kk2[i] = *p;
            }
        }

        float pf[16];
        #pragma unroll
        for (int h = 0; h < 4; ++h)
            #pragma unroll
            for (int i = 0; i < 4; ++i) {
                float s = kk[i].x * qf[h].x;
                s += kk[i].y * qf[h].y;
                s += kk[i].z * qf[h].z;
                s += kk[i].w * qf[h].w;
                pf[(h << 2) | i] = s;
            }
        float r8[8];
        #pragma unroll
        for (int j = 0; j < 8; ++j) {
            float snd = (c4 & 1) ? pf[2*j] : pf[2*j+1];
            float kp  = (c4 & 1) ? pf[2*j+1] : pf[2*j];
            r8[j] = kp + __shfl_xor_sync(0xffffffffu, snd, 1);
        }
        float r4[4];
        #pragma unroll
        for (int j = 0; j < 4; ++j) {
            float snd = (c4 & 2) ? r8[2*j] : r8[2*j+1];
            float kp  = (c4 & 2) ? r8[2*j+1] : r8[2*j];
            r4[j] = kp + __shfl_xor_sync(0xffffffffu, snd, 2);
        }
        float r2v[2];
        #pragma unroll
        for (int j = 0; j < 2; ++j) {
            float snd = (c4 & 4) ? r4[2*j] : r4[2*j+1];
            float kp  = (c4 & 4) ? r4[2*j+1] : r4[2*j];
            r2v[j] = kp + __shfl_xor_sync(0xffffffffu, snd, 4);
        }
        float sc;
        {
            float snd = (c4 & 8) ? r2v[0] : r2v[1];
            float kp  = (c4 & 8) ? r2v[1] : r2v[0];
            sc = kp + __shfl_xor_sync(0xffffffffu, snd, 8);
        }

        float ph = __expf(sc);
        pshw[warp][(r2 + ((c4 & 3) << 1)) * 4 + (c4 >> 2)] = ph;
        s_acc += ph;

        if (tt < NT - 1) {
            #pragma unroll
            for (int i = 0; i < 4; ++i) {
                int row = wbase + r2 + (i << 1);
                cpasync16((uint32_t)__cvta_generic_to_shared(&Vsh[buf ^ 1][row][c4 << 2]),
                          (const void*)(vbase + (size_t)(l0 + TILE + row) * 512 + (c4 << 2)));
            }
            cpasync_commit();
            cpasync_wait<1>();
        } else {
            cpasync_wait<0>();
        }
        if (l0 + 63 == SP && warp == 7)
            *(float2*)&Vsh[buf][63][lane << 1] = *(const float2*)&vnsm[lane << 1];
        __syncwarp();

        #pragma unroll
        for (int r = 0; r < 8; ++r) {
            float4 p4 = *(const float4*)&pshw[warp][r << 2];
            float2 v2 = *(const float2*)&Vsh[buf][wbase + r][lane << 1];
            oa[0][0] += p4.x * v2.x; oa[0][1] += p4.x * v2.y;
            oa[1][0] += p4.y * v2.x; oa[1][1] += p4.y * v2.y;
            oa[2][0] += p4.z * v2.x; oa[2][1] += p4.z * v2.y;
            oa[3][0] += p4.w * v2.x; oa[3][1] += p4.w * v2.y;
        }
        __syncwarp();

        kk[0] = kk2[0]; kk[1] = kk2[1]; kk[2] = kk2[2]; kk[3] = kk2[3];
    }

    {
        float ps = s_acc;
        ps += __shfl_xor_sync(0xffffffffu, ps, 1);
        ps += __shfl_xor_sync(0xffffffffu, ps, 2);
        ps += __shfl_xor_sync(0xffffffffu, ps, 16);
        if ((lane & 3) == 0 && (lane & 16) == 0) wreds[warp][lane >> 2] = ps;
    }

    __syncthreads();
    float (*obuf)[256] = (float(*)[256])&Vsh[0][0][0];
    #pragma unroll
    for (int h = 0; h < 4; ++h)
        *(float2*)&obuf[warp][(h << 6) + (lane << 1)] = make_float2(oa[h][0], oa[h][1]);
    __syncthreads();
    {
        int h = t >> 6, dd = t & 63;
        float oo = 0.f;
        #pragma unroll
        for (int w = 0; w < 8; ++w) oo += obuf[w][t];
        g_part_o[(((b * NKV + kv) * NSPLIT + split) * REP + h) * HD + dd] = oo;
    }
    if (t < REP) {
        float ssum = 0.f;
        #pragma unroll
        for (int w = 0; w < 8; ++w) ssum += wreds[w][t];
        g_part_s[((b * NKV + kv) * NSPLIT + split) * REP + t] = ssum;
    }
}

// ---------------- O GEMM with fused split-combine X loader (86.5us version) ----------------
__global__ __launch_bounds__(256) void gemm_o_kernel(const float* __restrict__ W)
{
    __shared__ GemmSmem sm;
    __shared__ float srcp[32][4];

    const int jbase = blockIdx.x * 128;
    const int t = threadIdx.x, lane = t & 31, wid = t >> 5;
    const int kvg = blockIdx.y;
    const int kbeg = kvg * KCHUNK;

    if (t < 128) {
        int m = t >> 2, hh = t & 3;
        float S = 0.f;
        #pragma unroll
        for (int s = 0; s < NSPLIT; ++s)
            S += g_part_s[((m * NKV + kvg) * NSPLIT + s) * REP + hh];
        srcp[m][hh] = 1.f / S;
    }
    __syncthreads();

    float acc[2][2][4];
    #pragma unroll
    for (int m = 0; m < 2; ++m)
        #pragma unroll
        for (int n = 0; n < 2; ++n)
            #pragma unroll
            for (int i = 0; i < 4; ++i) acc[m][n][i] = 0.f;

    for (int kb = 0; kb < 4; ++kb) {
        const int k0 = kbeg + kb * 64;
        const int h = kb;
        #pragma unroll
        for (int i = 0; i < 2; ++i) {
            int idx = i * 256 + t;
            int m = idx >> 4, c = (idx & 15) << 2;
            float4 a = make_float4(0.f, 0.f, 0.f, 0.f);
            #pragma unroll
            for (int s = 0; s < NSPLIT; ++s) {
                float4 p = *(const float4*)
                    &g_part_o[(((m * NKV + kvg) * NSPLIT + s) * REP + h) * HD + c];
                a.x += p.x; a.y += p.y; a.z += p.z; a.w += p.w;
            }
            float r = srcp[m][h];
            a.x *= r; a.y *= r; a.z *= r; a.w *= r;
            split_store4(&sm.XsH[m][c], &sm.XsL[m][c], a);
        }
        #pragma unroll
        for (int i = 0; i < 8; ++i) {
            int idx = i * 256 + t;
            int kk = idx >> 5, nc = (idx & 31) << 2;
            float4 v = *(const float4*)&W[(size_t)(k0 + kk) * DIM + jbase + nc];
            split_store4(&sm.WsH[kk][nc], &sm.WsL[kk][nc], v);
        }
        __syncthreads();
        gemm_mma_steps(&sm, lane, wid, acc);
        __syncthreads();
    }

    const int gid = lane >> 2, tig = lane & 3;
    const int ks = blockIdx.y;
    #pragma unroll
    for (int m = 0; m < 2; ++m) {
        int row = m * 16 + gid;
        #pragma unroll
        for (int n = 0; n < 2; ++n) {
            int col = jbase + wid * 16 + n * 8 + tig * 2;
            *(float2*)&g_o_part[(size_t)(ks * 32 + row    ) * DIM + col]
                = make_float2(acc[m][n][0], acc[m][n][1]);
            *(float2*)&g_o_part[(size_t)(ks * 32 + row + 8) * DIM + col]
                = make_float2(acc[m][n][2], acc[m][n][3]);
        }
    }
}

// ---------------- final O-proj partial reduce ----------------
__global__ __launch_bounds__(128) void oreduce_kernel(float* __restrict__ out)
{
    int i4 = blockIdx.x * 128 + threadIdx.x;
    float4 v = make_float4(0.f, 0.f, 0.f, 0.f);
    #pragma unroll
    for (int s = 0; s < KSPLIT; ++s) {
        float4 p = *(const float4*)&g_o_part[s * BATCH * DIM + i4 * 4];
        v.x += p.x; v.y += p.y; v.z += p.z; v.w += p.w;
    }
    *(float4*)&out[i4 * 4] = v;
}

// ---------------- launch ----------------
extern "C" void kernel_launch(void* const* d_in, const int* in_sizes, int n_in,
                              void* d_out, int out_size)
{
    const float* x  = (const float*)d_in[0];
    const float* qw = (const float*)d_in[1];
    const float* kw = (const float*)d_in[2];
    const float* vw = (const float*)d_in[3];
    const float* ow = (const float*)d_in[4];
    const float* ck = (const float*)d_in[5];
    const float* cv = (const float*)d_in[6];
    float* out = (float*)d_out;

    gemm_qkv_kernel<<<dim3(24, QKSPL), 256>>>(x, qw, kw, vw);
    attn_kernel<<<dim3(NSPLIT, NKV, BATCH), 256>>>(ck, cv);
    gemm_o_kernel<<<dim3(16, KSPLIT), 256>>>(ow);
    oreduce_kernel<<<128, 128>>>(out);
}